// round 6
// baseline (speedup 1.0000x reference)
#include <cuda_runtime.h>
#include <cuda_bf16.h>

#define B_  64
#define T_  262144
#define C_  3
#define K_  16384
#define H_  32

#define NSM_      148
#define CTAS_SM_  6
#define BLOCK_    256

#define BUCK_SH   9
#define NBUCK     512                      // buckets per batch (6KB regions)
#define NCTR      (B_ * NBUCK)             // 32768 counters

// Scratch (no cudaMalloc allowed): counters, cursors, packed work items.
__device__ int      g_count[NCTR];
__device__ int      g_cursor[NCTR];
__device__ unsigned g_pairs[B_ * K_];      // id (18b) | k<<18 (14b)

// ---------------------------------------------------------------- pre-passes
__global__ void kzero() {
    int i = blockIdx.x * 256 + threadIdx.x;
    if (i < NCTR) g_count[i] = 0;
}

__global__ void khist(const int* __restrict__ ids) {
    int i = blockIdx.x * 256 + threadIdx.x;           // handles 4 ids
    int4 v = reinterpret_cast<const int4*>(ids)[i];
    int base = (i >> 12) * NBUCK;                     // batch = (4i)>>14
    atomicAdd(&g_count[base + (v.x >> BUCK_SH)], 1);
    atomicAdd(&g_count[base + (v.y >> BUCK_SH)], 1);
    atomicAdd(&g_count[base + (v.z >> BUCK_SH)], 1);
    atomicAdd(&g_count[base + (v.w >> BUCK_SH)], 1);
}

__global__ __launch_bounds__(1024) void kscan() {     // single CTA
    __shared__ int warp_sums[32];
    const int tid  = threadIdx.x;
    const int lane = tid & 31, wid = tid >> 5;
    const int CH   = NCTR / 1024;                     // 32 counters/thread
    const int base = tid * CH;
    int sum = 0;
    for (int i = 0; i < CH; i++) sum += g_count[base + i];
    int v = sum;                                      // warp inclusive scan
    #pragma unroll
    for (int o = 1; o < 32; o <<= 1) {
        int n = __shfl_up_sync(~0u, v, o);
        if (lane >= o) v += n;
    }
    if (lane == 31) warp_sums[wid] = v;
    __syncthreads();
    if (wid == 0) {
        int w = warp_sums[lane];
        #pragma unroll
        for (int o = 1; o < 32; o <<= 1) {
            int n = __shfl_up_sync(~0u, w, o);
            if (lane >= o) w += n;
        }
        warp_sums[lane] = w;
    }
    __syncthreads();
    int run = v - sum + (wid > 0 ? warp_sums[wid - 1] : 0);  // exclusive base
    for (int i = 0; i < CH; i++) {
        g_cursor[base + i] = run;
        run += g_count[base + i];
    }
}

__global__ void kscatter(const int* __restrict__ ids) {
    int i = blockIdx.x * 256 + threadIdx.x;           // handles 4 ids
    int4 v = reinterpret_cast<const int4*>(ids)[i];
    int base = (i >> 12) * NBUCK;
    unsigned k0 = (unsigned)((i << 2) & (K_ - 1));
    int p;
    p = atomicAdd(&g_cursor[base + (v.x >> BUCK_SH)], 1);
    g_pairs[p] = (unsigned)v.x | ((k0 + 0u) << 18);
    p = atomicAdd(&g_cursor[base + (v.y >> BUCK_SH)], 1);
    g_pairs[p] = (unsigned)v.y | ((k0 + 1u) << 18);
    p = atomicAdd(&g_cursor[base + (v.z >> BUCK_SH)], 1);
    g_pairs[p] = (unsigned)v.z | ((k0 + 2u) << 18);
    p = atomicAdd(&g_cursor[base + (v.w >> BUCK_SH)], 1);
    g_pairs[p] = (unsigned)v.w | ((k0 + 3u) << 18);
}

// ------------------------------------------------------------------- gather
#define POOL3(f, S, p0, p1, p2)                                              \
    p0 = f[(S)+0] + f[(S)+3] + f[(S)+6] + f[(S)+9]  + f[(S)+12];             \
    p1 = f[(S)+1] + f[(S)+4] + f[(S)+7] + f[(S)+10] + f[(S)+13];             \
    p2 = f[(S)+2] + f[(S)+5] + f[(S)+8] + f[(S)+11] + f[(S)+14];

__device__ __forceinline__ void gather_pool(
    const float* __restrict__ xb, int id, float& p0, float& p1, float& p2)
{
    if (id >= 2 && id <= T_ - 7) {
        const size_t f0 = (size_t)(id - 2) * 3;
        const int    sh = (int)(f0 & 3);
        const float4* p4 = reinterpret_cast<const float4*>(xb + (f0 & ~(size_t)3));
        float4 c0 = __ldcg(p4 + 0);
        float4 c1 = __ldcg(p4 + 1);
        float4 c2 = __ldcg(p4 + 2);
        float4 c3 = __ldcg(p4 + 3);
        float4 c4 = make_float4(0.f, 0.f, 0.f, 0.f);
        if (sh >= 2) c4 = __ldcg(p4 + 4);
        float f[20] = { c0.x, c0.y, c0.z, c0.w,
                        c1.x, c1.y, c1.z, c1.w,
                        c2.x, c2.y, c2.z, c2.w,
                        c3.x, c3.y, c3.z, c3.w,
                        c4.x, c4.y, c4.z, c4.w };
        switch (sh) {
            case 0:  { POOL3(f, 0, p0, p1, p2) } break;
            case 1:  { POOL3(f, 1, p0, p1, p2) } break;
            case 2:  { POOL3(f, 2, p0, p1, p2) } break;
            default: { POOL3(f, 3, p0, p1, p2) } break;
        }
        p0 *= 0.2f; p1 *= 0.2f; p2 *= 0.2f;
    } else {
        float s0 = 0.f, s1 = 0.f, s2 = 0.f, cnt = 0.f;
        #pragma unroll
        for (int o = -2; o <= 2; o++) {
            int pos = id + o;
            if (pos >= 0 && pos < T_) {
                const float* r = xb + (size_t)pos * 3;
                s0 += r[0]; s1 += r[1]; s2 += r[2]; cnt += 1.0f;
            }
        }
        const float inv = 1.0f / cnt;
        p0 = s0 * inv; p1 = s1 * inv; p2 = s2 * inv;
    }
}

__global__ __launch_bounds__(BLOCK_, CTAS_SM_) void kmain(
    const float* __restrict__ x,
    const float* __restrict__ W1, const float* __restrict__ b1,
    const float* __restrict__ W2, const float* __restrict__ b2,
    float* __restrict__ out)
{
    __shared__ __align__(16) float sW1[C_ * H_];
    __shared__ __align__(16) float sB1[H_];
    __shared__ __align__(16) float sW2[H_];
    __shared__ float sB2;

    const int tid = threadIdx.x;
    if (tid < 96)        sW1[tid]       = W1[tid];
    else if (tid < 128)  sB1[tid - 96]  = b1[tid - 96];
    else if (tid < 160)  sW2[tid - 128] = W2[tid - 128];
    else if (tid == 160) sB2            = b2[0];
    __syncthreads();

    const float4* wA = reinterpret_cast<const float4*>(sW1);
    const float4* wB = reinterpret_cast<const float4*>(sW1 + 32);
    const float4* wC = reinterpret_cast<const float4*>(sW1 + 64);
    const float4* vb = reinterpret_cast<const float4*>(sB1);
    const float4* v2 = reinterpret_cast<const float4*>(sW2);
    const uint2* pr2 = reinterpret_cast<const uint2*>(g_pairs);

    const int NT     = (B_ * K_) / 2;                 // pairs of work items
    const int stride = gridDim.x * BLOCK_;
    int t = blockIdx.x * BLOCK_ + tid;

    uint2 pk = pr2[t];
    for (;;) {
        const int nt    = t + stride;
        const bool more = (nt < NT);

        const int b = t >> 13;                        // 16384-aligned batch segs
        const float* xb = x + (size_t)b * ((size_t)T_ * C_);

        const int idA = (int)(pk.x & 0x3FFFFu);
        const int kA  = (int)(pk.x >> 18);
        const int idB = (int)(pk.y & 0x3FFFFu);
        const int kB  = (int)(pk.y >> 18);

        float a0, a1, a2, q0, q1, q2;
        gather_pool(xb, idA, a0, a1, a2);
        gather_pool(xb, idB, q0, q1, q2);

        uint2 npk;
        if (more) npk = pr2[nt];

        float accA = sB2, accB = sB2;
        #pragma unroll
        for (int j = 0; j < H_ / 4; j++) {
            float4 wa = wA[j], wb_ = wB[j], wc = wC[j], dd = vb[j], ee = v2[j];
            float h;
            h = fmaf(a0, wa.x, fmaf(a1, wb_.x, fmaf(a2, wc.x, dd.x)));
            accA = fmaf(fmaxf(h, 0.f), ee.x, accA);
            h = fmaf(q0, wa.x, fmaf(q1, wb_.x, fmaf(q2, wc.x, dd.x)));
            accB = fmaf(fmaxf(h, 0.f), ee.x, accB);
            h = fmaf(a0, wa.y, fmaf(a1, wb_.y, fmaf(a2, wc.y, dd.y)));
            accA = fmaf(fmaxf(h, 0.f), ee.y, accA);
            h = fmaf(q0, wa.y, fmaf(q1, wb_.y, fmaf(q2, wc.y, dd.y)));
            accB = fmaf(fmaxf(h, 0.f), ee.y, accB);
            h = fmaf(a0, wa.z, fmaf(a1, wb_.z, fmaf(a2, wc.z, dd.z)));
            accA = fmaf(fmaxf(h, 0.f), ee.z, accA);
            h = fmaf(q0, wa.z, fmaf(q1, wb_.z, fmaf(q2, wc.z, dd.z)));
            accB = fmaf(fmaxf(h, 0.f), ee.z, accB);
            h = fmaf(a0, wa.w, fmaf(a1, wb_.w, fmaf(a2, wc.w, dd.w)));
            accA = fmaf(fmaxf(h, 0.f), ee.w, accA);
            h = fmaf(q0, wa.w, fmaf(q1, wb_.w, fmaf(q2, wc.w, dd.w)));
            accB = fmaf(fmaxf(h, 0.f), ee.w, accB);
        }

        const int obase = b << 14;                    // b * K_
        out[obase + kA] = accA;
        out[obase + kB] = accB;

        if (!more) break;
        t = nt;
        pk = npk;
    }
}

extern "C" void kernel_launch(void* const* d_in, const int* in_sizes, int n_in,
                              void* d_out, int out_size) {
    const float* x   = (const float*)d_in[0];
    const int*   ids = (const int*)d_in[1];
    const float* W1  = (const float*)d_in[2];
    const float* b1  = (const float*)d_in[3];
    const float* W2  = (const float*)d_in[4];
    const float* b2  = (const float*)d_in[5];
    float*       out = (float*)d_out;

    kzero   <<<NCTR / 256, 256>>>();
    khist   <<<(B_ * K_) / 4 / 256, 256>>>(ids);
    kscan   <<<1, 1024>>>();
    kscatter<<<(B_ * K_) / 4 / 256, 256>>>(ids);
    kmain   <<<NSM_ * CTAS_SM_, BLOCK_>>>(x, W1, b1, W2, b2, out);
}

// round 7
// speedup vs baseline: 2.7425x; 2.7425x over previous
#include <cuda_runtime.h>
#include <cuda_bf16.h>

#define B_  64
#define T_  262144
#define C_  3
#define K_  16384
#define H_  32

#define NSM_      148
#define CTAS_SM_  6
#define BLOCK_    256

#define BUCK_SH   9
#define NBUCK     512                      // buckets per batch (6KB x-regions)

// Scratch (no cudaMalloc allowed): packed sorted work items.
__device__ unsigned g_pairs[B_ * K_];      // id (18b) | k<<18 (14b)

// ---------------------------------------------------------- binning kernel
// One CTA per batch: smem counting sort of the batch's 16384 ids by id>>9.
__global__ __launch_bounds__(512) void kbin(const int* __restrict__ ids) {
    __shared__ int s_cnt[NBUCK];           // counters, then cursors
    __shared__ int s_warp[16];

    const int b    = blockIdx.x;
    const int tid  = threadIdx.x;
    const int lane = tid & 31, wid = tid >> 5;

    s_cnt[tid] = 0;                        // NBUCK == blockDim == 512
    __syncthreads();

    // Load 32 ids/thread, coalesced (8 x int4 with 512-thread stride).
    const int4* base4 = reinterpret_cast<const int4*>(ids + b * K_);
    int4 v[8];
    #pragma unroll
    for (int j = 0; j < 8; j++) v[j] = base4[j * 512 + tid];

    // Histogram (smem atomics, spread addresses).
    #pragma unroll
    for (int j = 0; j < 8; j++) {
        atomicAdd(&s_cnt[v[j].x >> BUCK_SH], 1);
        atomicAdd(&s_cnt[v[j].y >> BUCK_SH], 1);
        atomicAdd(&s_cnt[v[j].z >> BUCK_SH], 1);
        atomicAdd(&s_cnt[v[j].w >> BUCK_SH], 1);
    }
    __syncthreads();

    // Exclusive scan of 512 counters (warp shuffle + 16 warp sums).
    const int x = s_cnt[tid];
    int inc = x;
    #pragma unroll
    for (int o = 1; o < 32; o <<= 1) {
        int n = __shfl_up_sync(~0u, inc, o);
        if (lane >= o) inc += n;
    }
    if (lane == 31) s_warp[wid] = inc;
    __syncthreads();
    if (wid == 0 && lane < 16) {
        int w = s_warp[lane];
        #pragma unroll
        for (int o = 1; o < 16; o <<= 1) {
            int n = __shfl_up_sync(0xFFFFu, w, o);
            if (lane >= o) w += n;
        }
        s_warp[lane] = w;
    }
    __syncthreads();
    const int excl = inc - x + (wid > 0 ? s_warp[wid - 1] : 0);
    s_cnt[tid] = excl;                     // counters -> cursors
    __syncthreads();

    // Scatter packed (id | k<<18) into this batch's segment of g_pairs.
    const unsigned obase = (unsigned)(b * K_);
    #pragma unroll
    for (int j = 0; j < 8; j++) {
        const unsigned k0 = ((unsigned)(j * 512 + tid)) * 4u;
        int p;
        p = atomicAdd(&s_cnt[v[j].x >> BUCK_SH], 1);
        g_pairs[obase + p] = (unsigned)v[j].x | ((k0 + 0u) << 18);
        p = atomicAdd(&s_cnt[v[j].y >> BUCK_SH], 1);
        g_pairs[obase + p] = (unsigned)v[j].y | ((k0 + 1u) << 18);
        p = atomicAdd(&s_cnt[v[j].z >> BUCK_SH], 1);
        g_pairs[obase + p] = (unsigned)v[j].z | ((k0 + 2u) << 18);
        p = atomicAdd(&s_cnt[v[j].w >> BUCK_SH], 1);
        g_pairs[obase + p] = (unsigned)v[j].w | ((k0 + 3u) << 18);
    }
}

// ------------------------------------------------------------------- gather
#define POOL3(f, S, p0, p1, p2)                                              \
    p0 = f[(S)+0] + f[(S)+3] + f[(S)+6] + f[(S)+9]  + f[(S)+12];             \
    p1 = f[(S)+1] + f[(S)+4] + f[(S)+7] + f[(S)+10] + f[(S)+13];             \
    p2 = f[(S)+2] + f[(S)+5] + f[(S)+8] + f[(S)+11] + f[(S)+14];

__device__ __forceinline__ void gather_pool(
    const float* __restrict__ xb, int id, float& p0, float& p1, float& p2)
{
    if (id >= 2 && id <= T_ - 7) {
        const size_t f0 = (size_t)(id - 2) * 3;
        const int    sh = (int)(f0 & 3);
        const float4* p4 = reinterpret_cast<const float4*>(xb + (f0 & ~(size_t)3));
        float4 c0 = __ldcg(p4 + 0);
        float4 c1 = __ldcg(p4 + 1);
        float4 c2 = __ldcg(p4 + 2);
        float4 c3 = __ldcg(p4 + 3);
        float4 c4 = make_float4(0.f, 0.f, 0.f, 0.f);
        if (sh >= 2) c4 = __ldcg(p4 + 4);
        float f[20] = { c0.x, c0.y, c0.z, c0.w,
                        c1.x, c1.y, c1.z, c1.w,
                        c2.x, c2.y, c2.z, c2.w,
                        c3.x, c3.y, c3.z, c3.w,
                        c4.x, c4.y, c4.z, c4.w };
        switch (sh) {
            case 0:  { POOL3(f, 0, p0, p1, p2) } break;
            case 1:  { POOL3(f, 1, p0, p1, p2) } break;
            case 2:  { POOL3(f, 2, p0, p1, p2) } break;
            default: { POOL3(f, 3, p0, p1, p2) } break;
        }
        p0 *= 0.2f; p1 *= 0.2f; p2 *= 0.2f;
    } else {
        float s0 = 0.f, s1 = 0.f, s2 = 0.f, cnt = 0.f;
        #pragma unroll
        for (int o = -2; o <= 2; o++) {
            int pos = id + o;
            if (pos >= 0 && pos < T_) {
                const float* r = xb + (size_t)pos * 3;
                s0 += r[0]; s1 += r[1]; s2 += r[2]; cnt += 1.0f;
            }
        }
        const float inv = 1.0f / cnt;
        p0 = s0 * inv; p1 = s1 * inv; p2 = s2 * inv;
    }
}

__global__ __launch_bounds__(BLOCK_, CTAS_SM_) void kmain(
    const float* __restrict__ x,
    const float* __restrict__ W1, const float* __restrict__ b1,
    const float* __restrict__ W2, const float* __restrict__ b2,
    float* __restrict__ out)
{
    __shared__ __align__(16) float sW1[C_ * H_];
    __shared__ __align__(16) float sB1[H_];
    __shared__ __align__(16) float sW2[H_];
    __shared__ float sB2;

    const int tid = threadIdx.x;
    if (tid < 96)        sW1[tid]       = W1[tid];
    else if (tid < 128)  sB1[tid - 96]  = b1[tid - 96];
    else if (tid < 160)  sW2[tid - 128] = W2[tid - 128];
    else if (tid == 160) sB2            = b2[0];
    __syncthreads();

    const float4* wA = reinterpret_cast<const float4*>(sW1);
    const float4* wB = reinterpret_cast<const float4*>(sW1 + 32);
    const float4* wC = reinterpret_cast<const float4*>(sW1 + 64);
    const float4* vb = reinterpret_cast<const float4*>(sB1);
    const float4* v2 = reinterpret_cast<const float4*>(sW2);
    const uint2* pr2 = reinterpret_cast<const uint2*>(g_pairs);

    const int NT     = (B_ * K_) / 2;
    const int stride = gridDim.x * BLOCK_;
    int t = blockIdx.x * BLOCK_ + tid;

    uint2 pk = pr2[t];
    for (;;) {
        const int nt    = t + stride;
        const bool more = (nt < NT);

        const int b = t >> 13;                        // batch (segments aligned)
        const float* xb = x + (size_t)b * ((size_t)T_ * C_);

        const int idA = (int)(pk.x & 0x3FFFFu);
        const int kA  = (int)(pk.x >> 18);
        const int idB = (int)(pk.y & 0x3FFFFu);
        const int kB  = (int)(pk.y >> 18);

        float a0, a1, a2, q0, q1, q2;
        gather_pool(xb, idA, a0, a1, a2);
        gather_pool(xb, idB, q0, q1, q2);

        uint2 npk;
        if (more) npk = pr2[nt];

        float accA = sB2, accB = sB2;
        #pragma unroll
        for (int j = 0; j < H_ / 4; j++) {
            float4 wa = wA[j], wb_ = wB[j], wc = wC[j], dd = vb[j], ee = v2[j];
            float h;
            h = fmaf(a0, wa.x, fmaf(a1, wb_.x, fmaf(a2, wc.x, dd.x)));
            accA = fmaf(fmaxf(h, 0.f), ee.x, accA);
            h = fmaf(q0, wa.x, fmaf(q1, wb_.x, fmaf(q2, wc.x, dd.x)));
            accB = fmaf(fmaxf(h, 0.f), ee.x, accB);
            h = fmaf(a0, wa.y, fmaf(a1, wb_.y, fmaf(a2, wc.y, dd.y)));
            accA = fmaf(fmaxf(h, 0.f), ee.y, accA);
            h = fmaf(q0, wa.y, fmaf(q1, wb_.y, fmaf(q2, wc.y, dd.y)));
            accB = fmaf(fmaxf(h, 0.f), ee.y, accB);
            h = fmaf(a0, wa.z, fmaf(a1, wb_.z, fmaf(a2, wc.z, dd.z)));
            accA = fmaf(fmaxf(h, 0.f), ee.z, accA);
            h = fmaf(q0, wa.z, fmaf(q1, wb_.z, fmaf(q2, wc.z, dd.z)));
            accB = fmaf(fmaxf(h, 0.f), ee.z, accB);
            h = fmaf(a0, wa.w, fmaf(a1, wb_.w, fmaf(a2, wc.w, dd.w)));
            accA = fmaf(fmaxf(h, 0.f), ee.w, accA);
            h = fmaf(q0, wa.w, fmaf(q1, wb_.w, fmaf(q2, wc.w, dd.w)));
            accB = fmaf(fmaxf(h, 0.f), ee.w, accB);
        }

        const int obase = b << 14;                    // b * K_
        out[obase + kA] = accA;
        out[obase + kB] = accB;

        if (!more) break;
        t = nt;
        pk = npk;
    }
}

extern "C" void kernel_launch(void* const* d_in, const int* in_sizes, int n_in,
                              void* d_out, int out_size) {
    const float* x   = (const float*)d_in[0];
    const int*   ids = (const int*)d_in[1];
    const float* W1  = (const float*)d_in[2];
    const float* b1  = (const float*)d_in[3];
    const float* W2  = (const float*)d_in[4];
    const float* b2  = (const float*)d_in[5];
    float*       out = (float*)d_out;

    kbin <<<B_, 512>>>(ids);
    kmain<<<NSM_ * CTAS_SM_, BLOCK_>>>(x, W1, b1, W2, b2, out);
}